// round 14
// baseline (speedup 1.0000x reference)
#include <cuda_runtime.h>

#define T_DIM 4096
#define D_DIM 64
#define B_DIM 32
#define BLK 64
#define TP   (T_DIM / 2)        // 2048 point-pairs per batch row (u64 units)

typedef unsigned long long u64;   // two packed fp32 lanes (t, t+1)

__device__ __forceinline__ u64 fma2(u64 a, u64 b, u64 c) {
    u64 d; asm("fma.rn.f32x2 %0, %1, %2, %3;" : "=l"(d) : "l"(a), "l"(b), "l"(c)); return d;
}
__device__ __forceinline__ u64 mul2(u64 a, u64 b) {
    u64 d; asm("mul.rn.f32x2 %0, %1, %2;" : "=l"(d) : "l"(a), "l"(b)); return d;
}
__device__ __forceinline__ u64 add2(u64 a, u64 b) {
    u64 d; asm("add.rn.f32x2 %0, %1, %2;" : "=l"(d) : "l"(a), "l"(b)); return d;
}
#define HALF2 0x3F0000003F000000ULL   // {0.5f, 0.5f}

// Fused pyramid transition on packed lanes: fine F[2M] (u64 stride FS) ->
// coarse C[M], windows W = M .. 2M-1. R2-fused C build (each fine element
// read once). DS = dm u64 row stride. Gated dm load per p (the R12 pipeline
// was measured neutral; removed to save registers under the 146-reg cap).
template<int M, int FS, int DS>
__device__ __forceinline__ void transition(const u64* __restrict__ F,
                                           u64* __restrict__ C,
                                           const u64* __restrict__ pmv,
                                           const u64* __restrict__ dmb,
                                           int low, int up, u64& res)
{
    C[M - 1] = mul2(HALF2, add2(F[(2 * M - 2) * FS], F[(2 * M - 1) * FS]));

    u64 suf = 0ULL;
#pragma unroll
    for (int p = M - 1; p >= 1; p--) {
        const int W = M + p;
        u64 w = 0ULL;
        if (W >= low && W < up) w = dmb[(W - 1) * DS];
        u64 sc = 0ULL;
#pragma unroll
        for (int j = p; j < M; j++) sc = fma2(C[j], pmv[j + p], sc);
        res = fma2(w, sc, res);
        suf = add2(suf, w);
        const u64 a = F[(2 * p - 2) * FS], b = F[(2 * p - 1) * FS];
        res = fma2(fma2(a, pmv[2 * p - 2], mul2(b, pmv[2 * p - 1])), suf, res);
        C[p - 1] = mul2(HALF2, add2(a, b));
    }
    {   // p = 0: exact window W = M
        const int W = M;
        u64 w0 = 0ULL;
        if (W >= low && W < up) w0 = dmb[(W - 1) * DS];
        u64 sc = 0ULL;
#pragma unroll
        for (int j = 0; j < M; j++) sc = fma2(C[j], pmv[j], sc);
        res = fma2(w0, sc, res);
    }
}

__global__ __launch_bounds__(BLK, 7)   // 7 blocks/SM * 64 thr -> regs <= 146, single wave
void ContextGenerator_34875134444049_kernel(const float* __restrict__ rep_f,
                                            const float* __restrict__ dmask_f,
                                            const float* __restrict__ pmask_f,
                                            const int* __restrict__ lowp,
                                            const int* __restrict__ upp,
                                            float* __restrict__ out_f)
{
    const int gid = blockIdx.x * BLK + threadIdx.x;   // 0 .. B*TP-1 (pair id)
    const int b  = gid >> 11;                         // TP = 2048
    const int tp = gid & (TP - 1);
    const int base = b * (D_DIM * TP) + tp;           // u64 index

    const u64* __restrict__ rep = (const u64*)rep_f + base;
    const u64* __restrict__ dmb = (const u64*)dmask_f + base;
    const u64* __restrict__ pmb = (const u64*)pmask_f + base;

    const int low = *lowp;
    const int up  = *upp;

    // pm[63] is dead (fine terms reach pm[61], coarse reach pm[62])
    u64 pmv[63];
#pragma unroll
    for (int w = 0; w < 63; w++) pmv[w] = pmb[w * TP];

    u64 res = 0ULL;

    u64 L1[32]; transition<32, TP, TP>(rep, L1, pmv, dmb, low, up, res);
    u64 L2[16]; transition<16, 1, TP>(L1, L2, pmv, dmb, low, up, res);
    u64 L3[8];  transition<8, 1, TP>(L2, L3, pmv, dmb, low, up, res);
    u64 L4[4];  transition<4, 1, TP>(L3, L4, pmv, dmb, low, up, res);
    u64 L5[2];  transition<2, 1, TP>(L4, L5, pmv, dmb, low, up, res);

    // W = 1: d = deepest level (single packed element)
    const u64 x6 = mul2(HALF2, add2(L5[0], L5[1]));
    if (1 >= low && 1 < up) res = fma2(dmb[0], mul2(x6, pmv[0]), res);

    ((u64*)out_f)[gid] = res;   // two adjacent t outputs
}

extern "C" void kernel_launch(void* const* d_in, const int* in_sizes, int n_in,
                              void* d_out, int out_size)
{
    const float* rep   = (const float*)d_in[0];
    const float* dmask = (const float*)d_in[1];
    const float* pmask = (const float*)d_in[2];
    const int*   lowp  = (const int*)d_in[3];
    const int*   upp   = (const int*)d_in[4];
    float* out = (float*)d_out;

    const int pairs = B_DIM * TP;              // 65536
    ContextGenerator_34875134444049_kernel<<<pairs / BLK, BLK>>>(
        rep, dmask, pmask, lowp, upp, out);
}

// round 16
// speedup vs baseline: 1.6085x; 1.6085x over previous
#include <cuda_runtime.h>
#include <cstdint>

#define T_DIM 4096
#define D_DIM 64
#define B_DIM 32
#define BLK 128
#define TP   (T_DIM / 2)        // 2048 point-pairs per batch row (u64 units)
#define TILE_BYTES (D_DIM * BLK * 8)   // 64 rows x 128 u64 = 64 KB

typedef unsigned long long u64;   // two packed fp32 lanes (t, t+1)

__device__ __forceinline__ u64 fma2(u64 a, u64 b, u64 c) {
    u64 d; asm("fma.rn.f32x2 %0, %1, %2, %3;" : "=l"(d) : "l"(a), "l"(b), "l"(c)); return d;
}
__device__ __forceinline__ u64 mul2(u64 a, u64 b) {
    u64 d; asm("mul.rn.f32x2 %0, %1, %2;" : "=l"(d) : "l"(a), "l"(b)); return d;
}
__device__ __forceinline__ u64 add2(u64 a, u64 b) {
    u64 d; asm("add.rn.f32x2 %0, %1, %2;" : "=l"(d) : "l"(a), "l"(b)); return d;
}
#define HALF2 0x3F0000003F000000ULL   // {0.5f, 0.5f}

// Fused pyramid transition on packed lanes (R13 body, unchanged math).
template<int M, int FS, int DS>
__device__ __forceinline__ void transition(const u64* __restrict__ F,
                                           u64* __restrict__ C,
                                           const u64* __restrict__ pmv,
                                           const u64* __restrict__ dmb,
                                           int low, int up, u64& res)
{
    C[M - 1] = mul2(HALF2, add2(F[(2 * M - 2) * FS], F[(2 * M - 1) * FS]));

    u64 wbuf[4];
#pragma unroll
    for (int i = 0; i < (M < 4 ? M : 4); i++) {
        const int p = M - 1 - i;
        const int W = M + p;
        wbuf[p & 3] = (W >= low && W < up) ? dmb[(W - 1) * DS] : 0ULL;
    }

    u64 suf = 0ULL;
#pragma unroll
    for (int p = M - 1; p >= 1; p--) {
        const u64 w = wbuf[p & 3];
        if (p - 4 >= 0) {
            const int Wn = M + (p - 4);
            wbuf[(p - 4) & 3] = (Wn >= low && Wn < up) ? dmb[(Wn - 1) * DS] : 0ULL;
        }
        u64 sc = 0ULL;
#pragma unroll
        for (int j = p; j < M; j++) sc = fma2(C[j], pmv[j + p], sc);
        res = fma2(w, sc, res);
        suf = add2(suf, w);
        const u64 a = F[(2 * p - 2) * FS], b = F[(2 * p - 1) * FS];
        res = fma2(fma2(a, pmv[2 * p - 2], mul2(b, pmv[2 * p - 1])), suf, res);
        C[p - 1] = mul2(HALF2, add2(a, b));
    }
    {   // p = 0: exact window W = M
        const u64 w0 = wbuf[0];
        u64 sc = 0ULL;
#pragma unroll
        for (int j = 0; j < M; j++) sc = fma2(C[j], pmv[j], sc);
        res = fma2(w0, sc, res);
    }
}

__global__ void ContextGenerator_34875134444049_kernel(
        const float* __restrict__ rep_f,
        const float* __restrict__ dmask_f,
        const float* __restrict__ pmask_f,
        const int* __restrict__ lowp,
        const int* __restrict__ upp,
        float* __restrict__ out_f)
{
    extern __shared__ __align__(16) float srep[];   // 64 KB: [64 rows][256 floats]

    const int tid  = threadIdx.x;
    const int gid  = blockIdx.x * BLK + tid;          // pair id
    const int b    = gid >> 11;                       // TP = 2048
    const int tp   = gid & (TP - 1);
    const int base = b * (D_DIM * TP) + tp;           // u64 index

    // ---- async-stage the block's rep tile: 64 rows x 256 t (1 KB/row) ----
    {
        const int pair0 = blockIdx.x * BLK;
        const int bb = pair0 >> 11;
        const int t0 = (pair0 & (TP - 1)) * 2;        // multiple of 256
        const float* __restrict__ gsrc = rep_f + (size_t)bb * (D_DIM * T_DIM) + t0;
#pragma unroll
        for (int i = 0; i < 32; i++) {                // 4096 float4 / 128 thr
            const int idx = i * BLK + tid;
            const int row = idx >> 6;                 // 64 float4 per row
            const int c4  = idx & 63;
            const float* g = gsrc + row * T_DIM + c4 * 4;
            unsigned int saddr;
            asm("{ .reg .u64 t; cvta.to.shared.u64 t, %1; cvt.u32.u64 %0, t; }"
                : "=r"(saddr) : "l"(srep + idx * 4));
            asm volatile("cp.async.cg.shared.global [%0], [%1], 16;" :: "r"(saddr), "l"(g));
        }
        asm volatile("cp.async.commit_group;" ::: "memory");
    }

    const int low = *lowp;
    const int up  = *upp;

    const u64* __restrict__ dmb = (const u64*)dmask_f + base;
    const u64* __restrict__ pmb = (const u64*)pmask_f + base;

    // pm batch load overlaps with the async rep copy
    u64 pmv[63];
#pragma unroll
    for (int w = 0; w < 63; w++) pmv[w] = pmb[w * TP];

    asm volatile("cp.async.wait_group 0;" ::: "memory");
    __syncthreads();

    const u64* __restrict__ Fs = (const u64*)srep + tid;   // row stride = BLK u64

    u64 res = 0ULL;

    u64 L1[32]; transition<32, BLK, TP>(Fs, L1, pmv, dmb, low, up, res);
    u64 L2[16]; transition<16, 1, TP>(L1, L2, pmv, dmb, low, up, res);
    u64 L3[8];  transition<8, 1, TP>(L2, L3, pmv, dmb, low, up, res);
    u64 L4[4];  transition<4, 1, TP>(L3, L4, pmv, dmb, low, up, res);
    u64 L5[2];  transition<2, 1, TP>(L4, L5, pmv, dmb, low, up, res);

    // W = 1: d = deepest level (single packed element)
    const u64 x6 = mul2(HALF2, add2(L5[0], L5[1]));
    if (1 >= low && 1 < up) res = fma2(dmb[0], mul2(x6, pmv[0]), res);

    ((u64*)out_f)[gid] = res;   // two adjacent t outputs
}

extern "C" void kernel_launch(void* const* d_in, const int* in_sizes, int n_in,
                              void* d_out, int out_size)
{
    const float* rep   = (const float*)d_in[0];
    const float* dmask = (const float*)d_in[1];
    const float* pmask = (const float*)d_in[2];
    const int*   lowp  = (const int*)d_in[3];
    const int*   upp   = (const int*)d_in[4];
    float* out = (float*)d_out;

    cudaFuncSetAttribute(ContextGenerator_34875134444049_kernel,
                         cudaFuncAttributeMaxDynamicSharedMemorySize, TILE_BYTES);

    const int pairs = B_DIM * TP;              // 65536
    ContextGenerator_34875134444049_kernel<<<pairs / BLK, BLK, TILE_BYTES>>>(
        rep, dmask, pmask, lowp, upp, out);
}